// round 3
// baseline (speedup 1.0000x reference)
#include <cuda_runtime.h>
#include <math.h>

#define LQ 4096
#define EPSF 1e-5f

// ---------------- scratch (device globals; no runtime allocation) ----------------
__device__ float g_u [8*128*4096];   // pre-conv u, planar [s][d][l]
__device__ float g_z [8*128*4096];   // z, planar
__device__ float g_us[8*128*4096];   // silu(conv(u))
__device__ float g_dt[8*128*4096];   // softplus dt
__device__ float g_y [8*128*4096];   // scan output y
__device__ float g_Bl[8*4096*16];    // B, layout [s][l][k]
__device__ float g_Cl[8*4096*16];    // C, layout [s][l][k]
__device__ float g_mo[8*64*4096];    // mamba out + skip, planar [s][cq][l]
__device__ float g_mu1[8192], g_rs1[8192], g_mu2[8192], g_rs2[8192];
__device__ float g_P[8*128*16*32], g_S[8*128*16*32], g_H[8*128*16*32];
__device__ float g_Wg [4*256*64];    // g-scaled in_proj per part
__device__ float g_a1 [4*256], g_b1v[4*256];
__device__ float g_W2 [192*128];     // fused dt(128) + B(16) + C(16) + pad(32) weights
__device__ float g_bias2[192];
__device__ float g_Gm [256*256];     // g-scaled proj_w
__device__ float g_a2 [256], g_b2v[256];

// ---------------- precompute kernels ----------------
__global__ void k0a(const float* Wi, const float* lg, const float* lb) {
    int p = blockIdx.x;        // 0..3
    int e = threadIdx.x;       // 0..255
    float al = 0.f, be = 0.f;
    for (int cq = 0; cq < 64; cq++) {
        float w = Wi[e*64 + cq];
        int c = p*64 + cq;
        float wg = lg[c] * w;
        g_Wg[(p*256 + e)*64 + cq] = wg;
        al += wg;
        be += lb[c] * w;
    }
    g_a1[p*256 + e] = al;
    g_b1v[p*256 + e] = be;
}

__global__ void k0b(const float* dtw, const float* dtb, const float* xpw) {
    int idx = blockIdx.x*256 + threadIdx.x;
    if (idx < 192*128) {
        int row = idx >> 7, col = idx & 127;
        float v = 0.f;
        if (row < 128) {
            for (int r = 0; r < 4; r++) v += dtw[row*4 + r] * xpw[r*128 + col];
        } else if (row < 160) {
            v = xpw[(row - 124)*128 + col];   // rows 4..35 of x_proj_w (B then C)
        }
        g_W2[idx] = v;
    }
    if (idx < 192) g_bias2[idx] = (idx < 128) ? dtb[idx] : 0.f;
}

__global__ void k0c(const float* pw, const float* pb, const float* lg, const float* lb) {
    int o = threadIdx.x; // 0..255
    float al = 0.f, be = 0.f;
    for (int c = 0; c < 256; c++) {
        float w = pw[o*256 + c];
        float gm = lg[c] * w;
        g_Gm[o*256 + c] = gm;
        al += gm;
        be += lb[c] * w;
    }
    g_a2[o] = al;
    g_b2v[o] = be + pb[o];
}

// ---------------- layernorm stats ----------------
__global__ void kstats1(const float* x) {
    int i = blockIdx.x*256 + threadIdx.x;   // 8192 = (b,l)
    int b = i >> 12, l = i & 4095;
    const float* p = x + (size_t)b*256*LQ + l;
    float s = 0.f, ss = 0.f;
    for (int c = 0; c < 256; c++) {
        float v = p[(size_t)c*LQ];
        s += v; ss += v*v;
    }
    float mu = s * (1.f/256.f);
    float var = ss * (1.f/256.f) - mu*mu;
    g_mu1[i] = mu;
    g_rs1[i] = rsqrtf(var + EPSF);
}

__global__ void kstats2() {
    int i = blockIdx.x*256 + threadIdx.x;
    int b = i >> 12, l = i & 4095;
    float s = 0.f, ss = 0.f;
    for (int c = 0; c < 256; c++) {
        int plane = ((c >> 6)*2 + b)*64 + (c & 63);
        float v = g_mo[((size_t)plane << 12) + l];
        s += v; ss += v*v;
    }
    float mu = s * (1.f/256.f);
    float var = ss * (1.f/256.f) - mu*mu;
    g_mu2[i] = mu;
    g_rs2[i] = rsqrtf(var + EPSF);
}

// ---------------- shared GEMM micro-kernel ----------------
#define GEMM_TILE_COMPUTE() \
    _Pragma("unroll 8") \
    for (int kk = 0; kk < 64; kk++) { \
        float4 bv = *(const float4*)&Is[kk][tx << 2]; \
        float a0 = Ws[kk][(ty<<2)+0], a1 = Ws[kk][(ty<<2)+1]; \
        float a2 = Ws[kk][(ty<<2)+2], a3 = Ws[kk][(ty<<2)+3]; \
        acc[0][0] += a0*bv.x; acc[0][1] += a0*bv.y; acc[0][2] += a0*bv.z; acc[0][3] += a0*bv.w; \
        acc[1][0] += a1*bv.x; acc[1][1] += a1*bv.y; acc[1][2] += a1*bv.z; acc[1][3] += a1*bv.w; \
        acc[2][0] += a2*bv.x; acc[2][1] += a2*bv.y; acc[2][2] += a2*bv.z; acc[2][3] += a2*bv.w; \
        acc[3][0] += a3*bv.x; acc[3][1] += a3*bv.y; acc[3][2] += a3*bv.z; acc[3][3] += a3*bv.w; \
    }

// ---------------- G1: in_proj with LN1 folded -> u_raw, z ----------------
__global__ void kG1(const float* x) {
    int s = blockIdx.z, p = s >> 1, b = s & 1;
    int e0 = blockIdx.y << 6, l0 = blockIdx.x << 6;
    __shared__ float Ws[64][65];
    __shared__ float Is[64][68];
    int t = threadIdx.x, tx = t & 15, ty = t >> 4;
    float acc[4][4];
    #pragma unroll
    for (int i = 0; i < 4; i++)
        #pragma unroll
        for (int j = 0; j < 4; j++) acc[i][j] = 0.f;

    const float* Wb = g_Wg + p*256*64;
    const float* Ib = x + (size_t)b*256*LQ + (size_t)(p*64)*LQ;
    for (int idx = t; idx < 4096; idx += 256) {
        int e = idx >> 6, k = idx & 63;
        Ws[k][e] = Wb[(e0 + e)*64 + k];
    }
    for (int idx = t; idx < 4096; idx += 256) {
        int k = idx >> 6, l = idx & 63;
        Is[k][l] = Ib[(size_t)k*LQ + l0 + l];
    }
    __syncthreads();
    GEMM_TILE_COMPUTE();

    #pragma unroll
    for (int j = 0; j < 4; j++) {
        int l = l0 + (tx << 2) + j;
        float mu = g_mu1[(b << 12) + l], rs = g_rs1[(b << 12) + l];
        #pragma unroll
        for (int i = 0; i < 4; i++) {
            int e = e0 + (ty << 2) + i;
            float v = rs*acc[i][j] + (g_b1v[p*256 + e] - mu*rs*g_a1[p*256 + e]);
            if (e < 128) g_u[((size_t)(s*128 + e) << 12) + l] = v;
            else         g_z[((size_t)(s*128 + e - 128) << 12) + l] = v;
        }
    }
}

// ---------------- causal depthwise conv + silu ----------------
__global__ void kconv(const float* cw, const float* cb) {
    size_t idx = (size_t)blockIdx.x*256 + threadIdx.x;  // 8*128*4096
    int l = (int)(idx & 4095);
    int sd = (int)(idx >> 12);
    int d = sd & 127;
    const float* up = g_u + ((size_t)sd << 12);
    float acc = cb[d];
    float w0 = cw[d*4+0], w1 = cw[d*4+1], w2 = cw[d*4+2], w3 = cw[d*4+3];
    if (l >= 3) acc += up[l-3]*w0;
    if (l >= 2) acc += up[l-2]*w1;
    if (l >= 1) acc += up[l-1]*w2;
    acc += up[l]*w3;
    g_us[idx] = acc / (1.f + __expf(-acc));   // silu
}

// ---------------- G2: fused (dt_proj∘x_proj) + B + C ----------------
__global__ void kG2() {
    int s = blockIdx.z;
    int e0 = blockIdx.y << 6, l0 = blockIdx.x << 6;
    __shared__ float Ws[64][65];
    __shared__ float Is[64][68];
    int t = threadIdx.x, tx = t & 15, ty = t >> 4;
    float acc[4][4];
    #pragma unroll
    for (int i = 0; i < 4; i++)
        #pragma unroll
        for (int j = 0; j < 4; j++) acc[i][j] = 0.f;

    const float* Ib = g_us + (size_t)s*128*LQ;
    for (int kc = 0; kc < 128; kc += 64) {
        __syncthreads();
        for (int idx = t; idx < 4096; idx += 256) {
            int e = idx >> 6, k = idx & 63;
            Ws[k][e] = g_W2[(e0 + e)*128 + kc + k];
        }
        for (int idx = t; idx < 4096; idx += 256) {
            int k = idx >> 6, l = idx & 63;
            Is[k][l] = Ib[(size_t)(kc + k)*LQ + l0 + l];
        }
        __syncthreads();
        GEMM_TILE_COMPUTE();
    }

    #pragma unroll
    for (int i = 0; i < 4; i++) {
        int e = e0 + (ty << 2) + i;
        #pragma unroll
        for (int j = 0; j < 4; j++) {
            int l = l0 + (tx << 2) + j;
            float a = acc[i][j];
            if (e < 128) {
                float v = a + g_bias2[e];
                v = (v > 20.f) ? v : log1pf(__expf(v));  // softplus
                g_dt[((size_t)(s*128 + e) << 12) + l] = v;
            } else if (e < 144) {
                g_Bl[(((size_t)s << 12) + l)*16 + (e - 128)] = a;
            } else if (e < 160) {
                g_Cl[(((size_t)s << 12) + l)*16 + (e - 144)] = a;
            }
        }
    }
}

// ---------------- scan pass 1: per-chunk (P, S) ----------------
__global__ void kscan1(const float* Alog) {
    int tid = blockIdx.x*256 + threadIdx.x;   // 131072 threads
    int lane4 = tid & 3;
    int g = tid >> 2;
    int ch = g & 31;
    int sd = g >> 5;
    int d = sd & 127;
    int s = sd >> 7;
    int kb = lane4 << 2;
    float A1[4];
    #pragma unroll
    for (int j = 0; j < 4; j++) A1[j] = -__expf(Alog[d*16 + kb + j]);

    const float* dtp = g_dt + ((size_t)sd << 12) + (ch << 7);
    const float* up  = g_us + ((size_t)sd << 12) + (ch << 7);
    const float* Bp  = g_Bl + (((size_t)s << 12) + (ch << 7))*16 + kb;
    float P[4] = {1.f,1.f,1.f,1.f}, S[4] = {0.f,0.f,0.f,0.f};
    for (int st = 0; st < 128; st++) {
        float dtv = dtp[st], uv = up[st];
        float4 Bv = *(const float4*)(Bp + st*16);
        float du = dtv * uv;
        float bb[4] = {Bv.x, Bv.y, Bv.z, Bv.w};
        #pragma unroll
        for (int j = 0; j < 4; j++) {
            float a = __expf(dtv * A1[j]);
            P[j] *= a;
            S[j] = a*S[j] + du*bb[j];
        }
    }
    int base = (sd*16 + kb)*32 + ch;
    #pragma unroll
    for (int j = 0; j < 4; j++) { g_P[base + j*32] = P[j]; g_S[base + j*32] = S[j]; }
}

// ---------------- scan pass 2: chunk-level prefix ----------------
__global__ void kscan2() {
    int j = blockIdx.x*256 + threadIdx.x;   // 16384 = (s,d,k)
    int base = j*32;
    float H = 0.f;
    for (int ch = 0; ch < 32; ch++) {
        g_H[base + ch] = H;
        H = g_P[base + ch]*H + g_S[base + ch];
    }
}

// ---------------- scan pass 3: recompute with entry state, emit y ----------------
__global__ void kscan3(const float* Alog) {
    int tid = blockIdx.x*256 + threadIdx.x;
    int lane4 = tid & 3;
    int g = tid >> 2;
    int ch = g & 31;
    int sd = g >> 5;
    int d = sd & 127;
    int s = sd >> 7;
    int kb = lane4 << 2;
    float A1[4];
    #pragma unroll
    for (int j = 0; j < 4; j++) A1[j] = -__expf(Alog[d*16 + kb + j]);

    const float* dtp = g_dt + ((size_t)sd << 12) + (ch << 7);
    const float* up  = g_us + ((size_t)sd << 12) + (ch << 7);
    const float* Bp  = g_Bl + (((size_t)s << 12) + (ch << 7))*16 + kb;
    const float* Cp  = g_Cl + (((size_t)s << 12) + (ch << 7))*16 + kb;
    float* yo = g_y + ((size_t)sd << 12) + (ch << 7);

    float h[4];
    int base = (sd*16 + kb)*32 + ch;
    #pragma unroll
    for (int j = 0; j < 4; j++) h[j] = g_H[base + j*32];

    for (int s4 = 0; s4 < 32; s4++) {
        float ysave = 0.f;
        #pragma unroll
        for (int q = 0; q < 4; q++) {
            int st = (s4 << 2) + q;
            float dtv = dtp[st], uv = up[st];
            float4 Bv = *(const float4*)(Bp + st*16);
            float4 Cv = *(const float4*)(Cp + st*16);
            float du = dtv * uv;
            float bb[4] = {Bv.x, Bv.y, Bv.z, Bv.w};
            float cc[4] = {Cv.x, Cv.y, Cv.z, Cv.w};
            float yl = 0.f;
            #pragma unroll
            for (int j = 0; j < 4; j++) {
                float a = __expf(dtv * A1[j]);
                h[j] = a*h[j] + du*bb[j];
                yl += h[j]*cc[j];
            }
            yl += __shfl_xor_sync(0xFFFFFFFFu, yl, 1);
            yl += __shfl_xor_sync(0xFFFFFFFFu, yl, 2);
            if (lane4 == q) ysave = yl;
        }
        yo[(s4 << 2) + lane4] = ysave;
    }
}

// ---------------- G3: elementwise gate + out_proj + skip ----------------
__global__ void kG3(const float* x, const float* Wo, const float* Dp,
                    const float* lg, const float* lb, const float* skip) {
    int s = blockIdx.z, p = s >> 1, b = s & 1;
    int l0 = blockIdx.x << 6;
    __shared__ float Ws[64][65];
    __shared__ float Is[64][68];
    int t = threadIdx.x, tx = t & 15, ty = t >> 4;
    float acc[4][4];
    #pragma unroll
    for (int i = 0; i < 4; i++)
        #pragma unroll
        for (int j = 0; j < 4; j++) acc[i][j] = 0.f;

    for (int kc = 0; kc < 128; kc += 64) {
        __syncthreads();
        for (int idx = t; idx < 4096; idx += 256) {
            int e = idx >> 6, k = idx & 63;
            Ws[k][e] = Wo[e*128 + kc + k];
        }
        for (int idx = t; idx < 4096; idx += 256) {
            int k = idx >> 6, l = idx & 63;
            int dd = kc + k;
            size_t off = ((size_t)(s*128 + dd) << 12) + l0 + l;
            float yv = g_y[off], uv = g_us[off], zv = g_z[off];
            float t1 = yv + Dp[dd]*uv;
            Is[k][l] = t1 * (zv / (1.f + __expf(-zv)));
        }
        __syncthreads();
        GEMM_TILE_COMPUTE();
    }

    float sk = skip[0];
    #pragma unroll
    for (int j = 0; j < 4; j++) {
        int l = l0 + (tx << 2) + j;
        float mu = g_mu1[(b << 12) + l], rs = g_rs1[(b << 12) + l];
        #pragma unroll
        for (int i = 0; i < 4; i++) {
            int e = (ty << 2) + i;
            int c = p*64 + e;
            float xv = x[(size_t)b*256*LQ + (size_t)c*LQ + l];
            float part = (xv - mu)*rs*lg[c] + lb[c];
            g_mo[((size_t)(s*64 + e) << 12) + l] = acc[i][j] + sk*part;
        }
    }
}

// ---------------- G4: final projection with LN2 folded ----------------
__global__ void kG4(float* out) {
    int b = blockIdx.z;
    int o0 = blockIdx.y << 6, l0 = blockIdx.x << 6;
    __shared__ float Ws[64][65];
    __shared__ float Is[64][68];
    int t = threadIdx.x, tx = t & 15, ty = t >> 4;
    float acc[4][4];
    #pragma unroll
    for (int i = 0; i < 4; i++)
        #pragma unroll
        for (int j = 0; j < 4; j++) acc[i][j] = 0.f;

    for (int kc = 0; kc < 256; kc += 64) {
        __syncthreads();
        int p = kc >> 6;
        for (int idx = t; idx < 4096; idx += 256) {
            int e = idx >> 6, k = idx & 63;
            Ws[k][e] = g_Gm[(o0 + e)*256 + kc + k];
        }
        for (int idx = t; idx < 4096; idx += 256) {
            int k = idx >> 6, l = idx & 63;
            Is[k][l] = g_mo[((size_t)((p*2 + b)*64 + k) << 12) + l0 + l];
        }
        __syncthreads();
        GEMM_TILE_COMPUTE();
    }

    #pragma unroll
    for (int j = 0; j < 4; j++) {
        int l = l0 + (tx << 2) + j;
        float mu = g_mu2[(b << 12) + l], rs = g_rs2[(b << 12) + l];
        #pragma unroll
        for (int i = 0; i < 4; i++) {
            int o = o0 + (ty << 2) + i;
            out[(size_t)b*256*LQ + (size_t)o*LQ + l] =
                rs*acc[i][j] + (g_b2v[o] - mu*rs*g_a2[o]);
        }
    }
}

// ---------------- launch ----------------
extern "C" void kernel_launch(void* const* d_in, const int* in_sizes, int n_in,
                              void* d_out, int out_size) {
    const float* x    = (const float*)d_in[0];
    const float* lg   = (const float*)d_in[1];
    const float* lb   = (const float*)d_in[2];
    const float* skip = (const float*)d_in[3];
    const float* Wi   = (const float*)d_in[4];
    const float* cw   = (const float*)d_in[5];
    const float* cb   = (const float*)d_in[6];
    const float* xpw  = (const float*)d_in[7];
    const float* dtw  = (const float*)d_in[8];
    const float* dtb  = (const float*)d_in[9];
    const float* Alog = (const float*)d_in[10];
    const float* Dp   = (const float*)d_in[11];
    const float* Wo   = (const float*)d_in[12];
    const float* pw   = (const float*)d_in[13];
    const float* pb   = (const float*)d_in[14];
    float* out = (float*)d_out;

    k0a<<<4, 256>>>(Wi, lg, lb);
    k0b<<<96, 256>>>(dtw, dtb, xpw);
    k0c<<<1, 256>>>(pw, pb, lg, lb);
    kstats1<<<32, 256>>>(x);
    kG1<<<dim3(64, 4, 8), 256>>>(x);
    kconv<<<16384, 256>>>(cw, cb);
    kG2<<<dim3(64, 3, 8), 256>>>();
    kscan1<<<512, 256>>>(Alog);
    kscan2<<<64, 256>>>();
    kscan3<<<512, 256>>>(Alog);
    kG3<<<dim3(64, 1, 8), 256>>>(x, Wo, Dp, lg, lb, skip);
    kstats2<<<32, 256>>>();
    kG4<<<dim3(64, 4, 2), 256>>>(out);
}